// round 2
// baseline (speedup 1.0000x reference)
#include <cuda_runtime.h>
#include <cuda.h>
#include <cstdint>

// ============================================================================
// MultiLoraLinear on GB300 (ptxas target = plain sm_103, so NO tcgen05).
// Path: TMA + mbarrier pipeline -> SMEM -> mma.sync m16n8k8 tf32 (fallback HMMA)
//   out[b, s, o] = sum_i x[b, s, i] * weight[adapter_ids[b], o, i]
// B=8, S=2048, IN=4096, OUT=64, L=16, all fp32.
// ============================================================================

#define DEVINL __device__ __forceinline__

namespace mlora {

constexpr int kB = 8, kS = 2048, kIN = 4096, kOUT = 64;
constexpr int TILE_M = 128;           // x rows per CTA
constexpr int TILE_K = 64;            // fp32 K elems per pipeline stage
constexpr int NITER  = kIN / TILE_K;  // 64
constexpr int NSTAGE = 3;

// Each stage: A = [128 rows x 64 k] fp32 stored as two sub-tiles of
// [128 x 32] (128B rows, TMA SW128); B(W) = [64 rows x 64 k] as two [64 x 32].
constexpr int A_SUB   = TILE_M * 32 * 4;        // 16384
constexpr int B_SUB   = kOUT  * 32 * 4;         //  8192
constexpr int A_BYTES = 2 * A_SUB;              // 32768
constexpr int B_BYTES = 2 * B_SUB;              // 16384
constexpr int STAGE_BYTES = A_BYTES + B_BYTES;  // 49152

constexpr int OFF_FULL  = 0;
constexpr int OFF_EMPTY = OFF_FULL + NSTAGE * 8;
constexpr int OFF_DATA  = 1024;                              // SW128 alignment
constexpr int SMEM_TOTAL = OFF_DATA + NSTAGE * STAGE_BYTES;  // 148480

DEVINL uint32_t smem_u32(const void* p) {
    uint32_t a;
    asm("{ .reg .u64 t; cvta.to.shared.u64 t, %1; cvt.u32.u64 %0, t; }"
        : "=r"(a) : "l"(p));
    return a;
}

DEVINL uint32_t elect_one() {
    uint32_t pred;
    asm volatile(
        "{\n\t.reg .pred p;\n\telect.sync _|p, 0xFFFFFFFF;\n\t"
        "selp.b32 %0, 1, 0, p;\n\t}"
        : "=r"(pred));
    return pred;
}

#define MBARRIER_INIT(mbar, count) \
    asm volatile("mbarrier.init.shared.b64 [%0], %1;" \
        :: "r"((uint32_t)(mbar)), "r"((uint32_t)(count)) : "memory")

#define MBARRIER_ARRIVE(mbar) \
    asm volatile("mbarrier.arrive.shared.b64 _, [%0];" \
        :: "r"((uint32_t)(mbar)) : "memory")

#define MBARRIER_EXPECT_TX(mbar, bytes) \
    asm volatile("mbarrier.arrive.expect_tx.shared.b64 _, [%0], %1;" \
        :: "r"((uint32_t)(mbar)), "r"((uint32_t)(bytes)) : "memory")

#define MBARRIER_WAIT_PARITY(mbar, parity) do {                                   \
    uint32_t _m = (uint32_t)(mbar);                                               \
    uint32_t _p = (uint32_t)(parity);                                             \
    uint32_t _done;                                                               \
    asm volatile(                                                                 \
        "{\n\t.reg .pred p;\n\t"                                                  \
        "mbarrier.try_wait.parity.acquire.cta.shared::cta.b64 p, [%1], %2;\n\t"   \
        "selp.b32 %0, 1, 0, p;\n\t}"                                              \
        : "=r"(_done) : "r"(_m), "r"(_p) : "memory");                             \
    if (!_done) {                                                                 \
        asm volatile(                                                             \
            "{\n\t.reg .pred P1;\n\t"                                             \
            "WAIT_LOOP_%=:\n\t"                                                   \
            "mbarrier.try_wait.parity.acquire.cta.shared::cta.b64 P1, [%0], %1, 0x989680;\n\t" \
            "@P1 bra.uni WAIT_DONE_%=;\n\t"                                       \
            "bra.uni WAIT_LOOP_%=;\n\t"                                           \
            "WAIT_DONE_%=:\n\t}"                                                  \
            :: "r"(_m), "r"(_p) : "memory");                                      \
    }                                                                             \
} while (0)

// Producer-side wait: post-wait SMEM writes are async-proxy (TMA) only.
#define MBARRIER_WAIT_PARITY_RELAXED(mbar, parity) do {                           \
    uint32_t _m = (uint32_t)(mbar);                                               \
    uint32_t _p = (uint32_t)(parity);                                             \
    uint32_t _done;                                                               \
    asm volatile(                                                                 \
        "{\n\t.reg .pred p;\n\t"                                                  \
        "mbarrier.try_wait.parity.relaxed.cta.shared::cta.b64 p, [%1], %2, 0x989680;\n\t" \
        "selp.b32 %0, 1, 0, p;\n\t}"                                              \
        : "=r"(_done) : "r"(_m), "r"(_p) : "memory");                             \
    if (!_done) {                                                                 \
        asm volatile(                                                             \
            "{\n\t.reg .pred P1;\n\t"                                             \
            "WAIT_LOOP_%=:\n\t"                                                   \
            "mbarrier.try_wait.parity.relaxed.cta.shared::cta.b64 P1, [%0], %1, 0x989680;\n\t" \
            "@P1 bra.uni WAIT_DONE_%=;\n\t"                                       \
            "bra.uni WAIT_LOOP_%=;\n\t"                                           \
            "WAIT_DONE_%=:\n\t}"                                                  \
            :: "r"(_m), "r"(_p) : "memory");                                      \
    }                                                                             \
} while (0)

#define TMA_LOAD_3D(smem_addr, tensor_map, cx, cy, cz, mbar) \
    asm volatile( \
        "cp.async.bulk.tensor.3d.shared::cta.global.tile.mbarrier::complete_tx::bytes " \
        "[%0], [%1, {%2, %3, %4}], [%5];" \
        :: "r"((uint32_t)(smem_addr)), "l"(tensor_map), \
           "r"((int32_t)(cx)), "r"((int32_t)(cy)), "r"((int32_t)(cz)), \
           "r"((uint32_t)(mbar)) \
        : "memory")

// Round-to-nearest tf32 conversion (halves + centers the tf32 truncation error).
#define CVT_TF32(dst, src) \
    asm("cvt.rna.tf32.f32 %0, %1;" : "=r"(dst) : "f"(src))

// m16n8k8 tf32 MMA, fp32 accumulate (baseline PTX; fallback HMMA on sm_103).
#define MMA_TF32(d, a, b) \
    asm volatile( \
        "mma.sync.aligned.m16n8k8.row.col.f32.tf32.tf32.f32 " \
        "{%0,%1,%2,%3}, {%4,%5,%6,%7}, {%8,%9}, {%0,%1,%2,%3};" \
        : "+f"((d)[0]), "+f"((d)[1]), "+f"((d)[2]), "+f"((d)[3]) \
        : "r"((a)[0]), "r"((a)[1]), "r"((a)[2]), "r"((a)[3]), \
          "r"((b)[0]), "r"((b)[1]))

// ============================================================================
// Kernel: 160 threads. Warps 0-3 compute (each owns a 32x64 output slab,
// accumulators in registers), warp 4 = TMA producer.
// grid = B * (S / TILE_M) = 128 CTAs. blockIdx.x = b*16 + row_tile.
// ============================================================================
__global__ void __launch_bounds__(160, 1) mlora_kernel(
    const __grid_constant__ CUtensorMap mapX,
    const __grid_constant__ CUtensorMap mapW,
    const int* __restrict__ adapter_ids,
    float* __restrict__ out)
{
    extern __shared__ char smem[];
    const uint32_t sb = smem_u32(smem);
    const int tid  = threadIdx.x;
    const int wid  = tid >> 5;
    const int lid  = tid & 31;
    const int b    = blockIdx.x >> 4;
    const int tile = blockIdx.x & 15;

    if (tid == 0) {
        #pragma unroll
        for (int s = 0; s < NSTAGE; s++) {
            MBARRIER_INIT(sb + OFF_FULL  + s * 8, 1);  // completed by TMA tx bytes
            MBARRIER_INIT(sb + OFF_EMPTY + s * 8, 4);  // 4 consumer warps arrive
        }
    }
    __syncthreads();

    if (wid == 4) {
        // ---------------- TMA producer ----------------
        if (elect_one()) {
            const int aid = adapter_ids[b];
            int st = 0, ph = 1;  // parity 1: fresh empty barriers pass immediately
            for (int it = 0; it < NITER; it++) {
                MBARRIER_WAIT_PARITY_RELAXED(sb + OFF_EMPTY + st * 8, ph);
                const uint32_t full = sb + OFF_FULL + st * 8;
                MBARRIER_EXPECT_TX(full, STAGE_BYTES);
                const uint32_t base = sb + OFF_DATA + st * STAGE_BYTES;
                #pragma unroll
                for (int t = 0; t < 2; t++) {
                    const int cx = it * TILE_K + t * 32;
                    TMA_LOAD_3D(base + t * A_SUB,           &mapX, cx, tile * TILE_M, b,   full);
                    TMA_LOAD_3D(base + A_BYTES + t * B_SUB, &mapW, cx, 0,             aid, full);
                }
                if (++st == NSTAGE) { st = 0; ph ^= 1; }
            }
        }
        return;
    }

    // ---------------- compute warps (wid 0..3) ----------------
    // Warp w computes output rows [w*32, w*32+32) x all 64 cols.
    // Fragment addressing (TMA SW128 on 128B rows => 16B granule g of row r
    // lands at g ^ (r&7); all fragment loads below are bank-conflict-free).
    const uint32_t sw   = (uint32_t)(lid >> 2) << 4;    // swizzle XOR (row&7)*16
    const uint32_t aRow = (uint32_t)(wid * 32 + (lid >> 2));
    const uint32_t bRow = (uint32_t)(lid >> 2);
    const uint32_t lk4  = (uint32_t)(lid & 3) * 4;

    float acc[2][8][4];
    #pragma unroll
    for (int mt = 0; mt < 2; mt++)
        #pragma unroll
        for (int nt = 0; nt < 8; nt++)
            #pragma unroll
            for (int i = 0; i < 4; i++) acc[mt][nt][i] = 0.0f;

    int st = 0, ph = 0;
    for (int it = 0; it < NITER; it++) {
        MBARRIER_WAIT_PARITY(sb + OFF_FULL + st * 8, ph);
        const char* base = smem + OFF_DATA + st * STAGE_BYTES;

        #pragma unroll
        for (int t = 0; t < 2; t++) {
            const char* aBase = base + t * A_SUB;
            const char* bBase = base + A_BYTES + t * B_SUB;
            #pragma unroll
            for (int ks = 0; ks < 4; ks++) {
                const uint32_t kb0 = (uint32_t)(ks * 32 + lk4) ^ sw;  // k = ks*8 + lane%4
                const uint32_t kb1 = kb0 ^ 16u;                       // k + 4

                // B fragments: one k8 x n8 frag per n-tile, shared across m-tiles.
                uint32_t bf[8][2];
                #pragma unroll
                for (int nt = 0; nt < 8; nt++) {
                    const char* rp = bBase + (bRow + nt * 8) * 128;
                    CVT_TF32(bf[nt][0], *reinterpret_cast<const float*>(rp + kb0));
                    CVT_TF32(bf[nt][1], *reinterpret_cast<const float*>(rp + kb1));
                }

                #pragma unroll
                for (int mt = 0; mt < 2; mt++) {
                    const char* ap = aBase + (aRow + mt * 16) * 128;
                    uint32_t af[4];
                    CVT_TF32(af[0], *reinterpret_cast<const float*>(ap + kb0));
                    CVT_TF32(af[1], *reinterpret_cast<const float*>(ap + 1024 + kb0));
                    CVT_TF32(af[2], *reinterpret_cast<const float*>(ap + kb1));
                    CVT_TF32(af[3], *reinterpret_cast<const float*>(ap + 1024 + kb1));
                    #pragma unroll
                    for (int nt = 0; nt < 8; nt++)
                        MMA_TF32(acc[mt][nt], af, bf[nt]);
                }
            }
        }

        // HMMA issue implies all this stage's LDS completed -> safe to recycle.
        __syncwarp();
        if (lid == 0) MBARRIER_ARRIVE(sb + OFF_EMPTY + st * 8);
        if (++st == NSTAGE) { st = 0; ph ^= 1; }
    }

    // ---------------- epilogue: registers -> GMEM ----------------
    // c0,c1 -> (row = lane/4, cols 2*(lane%4)+{0,1}); c2,c3 -> row+8.
    const size_t rowBase = (size_t)b * kS + (size_t)tile * TILE_M
                         + (size_t)wid * 32 + (size_t)(lid >> 2);
    const int colBase = (lid & 3) * 2;
    #pragma unroll
    for (int mt = 0; mt < 2; mt++) {
        #pragma unroll
        for (int nt = 0; nt < 8; nt++) {
            const size_t r0 = rowBase + mt * 16;
            float* p0 = out + r0 * kOUT + nt * 8 + colBase;
            float* p1 = out + (r0 + 8) * kOUT + nt * 8 + colBase;
            *reinterpret_cast<float2*>(p0) = make_float2(acc[mt][nt][0], acc[mt][nt][1]);
            *reinterpret_cast<float2*>(p1) = make_float2(acc[mt][nt][2], acc[mt][nt][3]);
        }
    }
}

}  // namespace mlora

// ============================================================================
// Host side
// ============================================================================

typedef CUresult (*PFN_encodeTiled)(
    CUtensorMap*, CUtensorMapDataType, cuuint32_t, void*,
    const cuuint64_t*, const cuuint64_t*, const cuuint32_t*, const cuuint32_t*,
    CUtensorMapInterleave, CUtensorMapSwizzle, CUtensorMapL2promotion,
    CUtensorMapFloatOOBfill);

extern "C" void kernel_launch(void* const* d_in, const int* in_sizes, int n_in,
                              void* d_out, int out_size) {
    (void)in_sizes; (void)n_in; (void)out_size;
    const float* x   = (const float*)d_in[0];
    const int*   ids = (const int*)  d_in[1];
    const float* w   = (const float*)d_in[2];
    float*       out = (float*)d_out;

    PFN_encodeTiled enc = nullptr;
    {
        void* p = nullptr;
        cudaDriverEntryPointQueryResult qr;
#if CUDART_VERSION >= 12050
        cudaGetDriverEntryPointByVersion("cuTensorMapEncodeTiled", &p, 12000,
                                         cudaEnableDefault, &qr);
#else
        cudaGetDriverEntryPoint("cuTensorMapEncodeTiled", &p, cudaEnableDefault, &qr);
#endif
        enc = (PFN_encodeTiled)p;
    }

    CUtensorMap mapX, mapW;
    {
        // x: [B, S, IN] fp32 contiguous; dim0 = IN. Box = 32 x 128 (128B rows, SW128).
        cuuint64_t dims[3]    = {(cuuint64_t)mlora::kIN, (cuuint64_t)mlora::kS,
                                 (cuuint64_t)mlora::kB};
        cuuint64_t strides[2] = {(cuuint64_t)mlora::kIN * 4,
                                 (cuuint64_t)mlora::kS * mlora::kIN * 4};
        cuuint32_t box[3]     = {32, (cuuint32_t)mlora::TILE_M, 1};
        cuuint32_t es[3]      = {1, 1, 1};
        enc(&mapX, CU_TENSOR_MAP_DATA_TYPE_FLOAT32, 3, (void*)x,
            dims, strides, box, es,
            CU_TENSOR_MAP_INTERLEAVE_NONE, CU_TENSOR_MAP_SWIZZLE_128B,
            CU_TENSOR_MAP_L2_PROMOTION_L2_128B, CU_TENSOR_MAP_FLOAT_OOB_FILL_NONE);
    }
    {
        // weight: [L, OUT, IN] fp32 contiguous; dim0 = IN. Box = 32 x 64.
        cuuint64_t dims[3]    = {(cuuint64_t)mlora::kIN, (cuuint64_t)mlora::kOUT,
                                 (cuuint64_t)16};
        cuuint64_t strides[2] = {(cuuint64_t)mlora::kIN * 4,
                                 (cuuint64_t)mlora::kOUT * mlora::kIN * 4};
        cuuint32_t box[3]     = {32, (cuuint32_t)mlora::kOUT, 1};
        cuuint32_t es[3]      = {1, 1, 1};
        enc(&mapW, CU_TENSOR_MAP_DATA_TYPE_FLOAT32, 3, (void*)w,
            dims, strides, box, es,
            CU_TENSOR_MAP_INTERLEAVE_NONE, CU_TENSOR_MAP_SWIZZLE_128B,
            CU_TENSOR_MAP_L2_PROMOTION_L2_128B, CU_TENSOR_MAP_FLOAT_OOB_FILL_NONE);
    }

    cudaFuncSetAttribute(mlora::mlora_kernel,
                         cudaFuncAttributeMaxDynamicSharedMemorySize,
                         mlora::SMEM_TOTAL);

    const int grid = mlora::kB * (mlora::kS / mlora::TILE_M);  // 128
    mlora::mlora_kernel<<<grid, 160, mlora::SMEM_TOTAL>>>(mapX, mapW, ids, out);
}

// round 3
// speedup vs baseline: 1.1075x; 1.1075x over previous
#include <cuda_runtime.h>
#include <cuda.h>
#include <cstdint>

// ============================================================================
// MultiLoraLinear on GB300 (ptxas target = plain sm_103, so NO tcgen05).
// TMA + mbarrier pipeline -> SMEM -> mma.sync m16n8k8 tf32 (fallback HMMA).
//   out[b, s, o] = sum_i x[b, s, i] * weight[adapter_ids[b], o, i]
// B=8, S=2048, IN=4096, OUT=64, L=16, all fp32.
//
// R3 changes vs R2 (61.3us, DRAM 59%, consumer-bound):
//   - B operand: skip cvt.rna, feed raw f32 bits to HMMA.TF32 (HW truncation).
//     Removes 128 of 384 hot-loop instructions per warp per stage. A keeps rna
//     so the systematic truncation bias stays at one operand (~ -2.4e-4).
//   - NSTAGE 3 -> 4 (197KB SMEM) for deeper TMA run-ahead.
// ============================================================================

#define DEVINL __device__ __forceinline__

namespace mlora {

constexpr int kB = 8, kS = 2048, kIN = 4096, kOUT = 64;
constexpr int TILE_M = 128;           // x rows per CTA
constexpr int TILE_K = 64;            // fp32 K elems per pipeline stage
constexpr int NITER  = kIN / TILE_K;  // 64
constexpr int NSTAGE = 4;

// Each stage: A = [128 rows x 64 k] fp32 stored as two sub-tiles of
// [128 x 32] (128B rows, TMA SW128); B(W) = [64 rows x 64 k] as two [64 x 32].
constexpr int A_SUB   = TILE_M * 32 * 4;        // 16384
constexpr int B_SUB   = kOUT  * 32 * 4;         //  8192
constexpr int A_BYTES = 2 * A_SUB;              // 32768
constexpr int B_BYTES = 2 * B_SUB;              // 16384
constexpr int STAGE_BYTES = A_BYTES + B_BYTES;  // 49152

constexpr int OFF_FULL  = 0;
constexpr int OFF_EMPTY = OFF_FULL + NSTAGE * 8;
constexpr int OFF_DATA  = 1024;                              // SW128 alignment
constexpr int SMEM_TOTAL = OFF_DATA + NSTAGE * STAGE_BYTES;  // 197632

DEVINL uint32_t smem_u32(const void* p) {
    uint32_t a;
    asm("{ .reg .u64 t; cvta.to.shared.u64 t, %1; cvt.u32.u64 %0, t; }"
        : "=r"(a) : "l"(p));
    return a;
}

DEVINL uint32_t elect_one() {
    uint32_t pred;
    asm volatile(
        "{\n\t.reg .pred p;\n\telect.sync _|p, 0xFFFFFFFF;\n\t"
        "selp.b32 %0, 1, 0, p;\n\t}"
        : "=r"(pred));
    return pred;
}

#define MBARRIER_INIT(mbar, count) \
    asm volatile("mbarrier.init.shared.b64 [%0], %1;" \
        :: "r"((uint32_t)(mbar)), "r"((uint32_t)(count)) : "memory")

#define MBARRIER_ARRIVE(mbar) \
    asm volatile("mbarrier.arrive.shared.b64 _, [%0];" \
        :: "r"((uint32_t)(mbar)) : "memory")

#define MBARRIER_EXPECT_TX(mbar, bytes) \
    asm volatile("mbarrier.arrive.expect_tx.shared.b64 _, [%0], %1;" \
        :: "r"((uint32_t)(mbar)), "r"((uint32_t)(bytes)) : "memory")

#define MBARRIER_WAIT_PARITY(mbar, parity) do {                                   \
    uint32_t _m = (uint32_t)(mbar);                                               \
    uint32_t _p = (uint32_t)(parity);                                             \
    uint32_t _done;                                                               \
    asm volatile(                                                                 \
        "{\n\t.reg .pred p;\n\t"                                                  \
        "mbarrier.try_wait.parity.acquire.cta.shared::cta.b64 p, [%1], %2;\n\t"   \
        "selp.b32 %0, 1, 0, p;\n\t}"                                              \
        : "=r"(_done) : "r"(_m), "r"(_p) : "memory");                             \
    if (!_done) {                                                                 \
        asm volatile(                                                             \
            "{\n\t.reg .pred P1;\n\t"                                             \
            "WAIT_LOOP_%=:\n\t"                                                   \
            "mbarrier.try_wait.parity.acquire.cta.shared::cta.b64 P1, [%0], %1, 0x989680;\n\t" \
            "@P1 bra.uni WAIT_DONE_%=;\n\t"                                       \
            "bra.uni WAIT_LOOP_%=;\n\t"                                           \
            "WAIT_DONE_%=:\n\t}"                                                  \
            :: "r"(_m), "r"(_p) : "memory");                                      \
    }                                                                             \
} while (0)

// Producer-side wait: post-wait SMEM writes are async-proxy (TMA) only.
#define MBARRIER_WAIT_PARITY_RELAXED(mbar, parity) do {                           \
    uint32_t _m = (uint32_t)(mbar);                                               \
    uint32_t _p = (uint32_t)(parity);                                             \
    uint32_t _done;                                                               \
    asm volatile(                                                                 \
        "{\n\t.reg .pred p;\n\t"                                                  \
        "mbarrier.try_wait.parity.relaxed.cta.shared::cta.b64 p, [%1], %2, 0x989680;\n\t" \
        "selp.b32 %0, 1, 0, p;\n\t}"                                              \
        : "=r"(_done) : "r"(_m), "r"(_p) : "memory");                             \
    if (!_done) {                                                                 \
        asm volatile(                                                             \
            "{\n\t.reg .pred P1;\n\t"                                             \
            "WAIT_LOOP_%=:\n\t"                                                   \
            "mbarrier.try_wait.parity.relaxed.cta.shared::cta.b64 P1, [%0], %1, 0x989680;\n\t" \
            "@P1 bra.uni WAIT_DONE_%=;\n\t"                                       \
            "bra.uni WAIT_LOOP_%=;\n\t"                                           \
            "WAIT_DONE_%=:\n\t}"                                                  \
            :: "r"(_m), "r"(_p) : "memory");                                      \
    }                                                                             \
} while (0)

#define TMA_LOAD_3D(smem_addr, tensor_map, cx, cy, cz, mbar) \
    asm volatile( \
        "cp.async.bulk.tensor.3d.shared::cta.global.tile.mbarrier::complete_tx::bytes " \
        "[%0], [%1, {%2, %3, %4}], [%5];" \
        :: "r"((uint32_t)(smem_addr)), "l"(tensor_map), \
           "r"((int32_t)(cx)), "r"((int32_t)(cy)), "r"((int32_t)(cz)), \
           "r"((uint32_t)(mbar)) \
        : "memory")

// Round-to-nearest tf32 conversion (A operand only: centers its error at 0).
#define CVT_TF32(dst, src) \
    asm("cvt.rna.tf32.f32 %0, %1;" : "=r"(dst) : "f"(src))

// m16n8k8 tf32 MMA, fp32 accumulate (baseline PTX; fallback HMMA on sm_103).
#define MMA_TF32(d, a, b) \
    asm volatile( \
        "mma.sync.aligned.m16n8k8.row.col.f32.tf32.tf32.f32 " \
        "{%0,%1,%2,%3}, {%4,%5,%6,%7}, {%8,%9}, {%0,%1,%2,%3};" \
        : "+f"((d)[0]), "+f"((d)[1]), "+f"((d)[2]), "+f"((d)[3]) \
        : "r"((a)[0]), "r"((a)[1]), "r"((a)[2]), "r"((a)[3]), \
          "r"((b)[0]), "r"((b)[1]))

// ============================================================================
// Kernel: 160 threads. Warps 0-3 compute (each owns a 32x64 output slab,
// accumulators in registers), warp 4 = TMA producer.
// grid = B * (S / TILE_M) = 128 CTAs. blockIdx.x = b*16 + row_tile.
// ============================================================================
__global__ void __launch_bounds__(160, 1) mlora_kernel(
    const __grid_constant__ CUtensorMap mapX,
    const __grid_constant__ CUtensorMap mapW,
    const int* __restrict__ adapter_ids,
    float* __restrict__ out)
{
    extern __shared__ char smem[];
    const uint32_t sb = smem_u32(smem);
    const int tid  = threadIdx.x;
    const int wid  = tid >> 5;
    const int lid  = tid & 31;
    const int b    = blockIdx.x >> 4;
    const int tile = blockIdx.x & 15;

    if (tid == 0) {
        #pragma unroll
        for (int s = 0; s < NSTAGE; s++) {
            MBARRIER_INIT(sb + OFF_FULL  + s * 8, 1);  // completed by TMA tx bytes
            MBARRIER_INIT(sb + OFF_EMPTY + s * 8, 4);  // 4 consumer warps arrive
        }
    }
    __syncthreads();

    if (wid == 4) {
        // ---------------- TMA producer ----------------
        if (elect_one()) {
            const int aid = adapter_ids[b];
            int st = 0, ph = 1;  // parity 1: fresh empty barriers pass immediately
            for (int it = 0; it < NITER; it++) {
                MBARRIER_WAIT_PARITY_RELAXED(sb + OFF_EMPTY + st * 8, ph);
                const uint32_t full = sb + OFF_FULL + st * 8;
                MBARRIER_EXPECT_TX(full, STAGE_BYTES);
                const uint32_t base = sb + OFF_DATA + st * STAGE_BYTES;
                #pragma unroll
                for (int t = 0; t < 2; t++) {
                    const int cx = it * TILE_K + t * 32;
                    TMA_LOAD_3D(base + t * A_SUB,           &mapX, cx, tile * TILE_M, b,   full);
                    TMA_LOAD_3D(base + A_BYTES + t * B_SUB, &mapW, cx, 0,             aid, full);
                }
                if (++st == NSTAGE) { st = 0; ph ^= 1; }
            }
        }
        return;
    }

    // ---------------- compute warps (wid 0..3) ----------------
    // Warp w computes output rows [w*32, w*32+32) x all 64 cols.
    // Fragment addressing (TMA SW128 on 128B rows => 16B granule g of row r
    // lands at g ^ (r&7); all fragment loads below are bank-conflict-free).
    const uint32_t sw   = (uint32_t)(lid >> 2) << 4;    // swizzle XOR (row&7)*16
    const uint32_t aRow = (uint32_t)(wid * 32 + (lid >> 2));
    const uint32_t bRow = (uint32_t)(lid >> 2);
    const uint32_t lk4  = (uint32_t)(lid & 3) * 4;

    float acc[2][8][4];
    #pragma unroll
    for (int mt = 0; mt < 2; mt++)
        #pragma unroll
        for (int nt = 0; nt < 8; nt++)
            #pragma unroll
            for (int i = 0; i < 4; i++) acc[mt][nt][i] = 0.0f;

    int st = 0, ph = 0;
    for (int it = 0; it < NITER; it++) {
        MBARRIER_WAIT_PARITY(sb + OFF_FULL + st * 8, ph);
        const char* base = smem + OFF_DATA + st * STAGE_BYTES;

        #pragma unroll
        for (int t = 0; t < 2; t++) {
            const char* aBase = base + t * A_SUB;
            const char* bBase = base + A_BYTES + t * B_SUB;
            #pragma unroll
            for (int ks = 0; ks < 4; ks++) {
                const uint32_t kb0 = (uint32_t)(ks * 32 + lk4) ^ sw;  // k = ks*8 + lane%4
                const uint32_t kb1 = kb0 ^ 16u;                       // k + 4

                // B fragments: raw f32 bits (HMMA.TF32 truncates in HW).
                uint32_t bf[8][2];
                #pragma unroll
                for (int nt = 0; nt < 8; nt++) {
                    const char* rp = bBase + (bRow + nt * 8) * 128;
                    bf[nt][0] = *reinterpret_cast<const uint32_t*>(rp + kb0);
                    bf[nt][1] = *reinterpret_cast<const uint32_t*>(rp + kb1);
                }

                #pragma unroll
                for (int mt = 0; mt < 2; mt++) {
                    const char* ap = aBase + (aRow + mt * 16) * 128;
                    uint32_t af[4];
                    CVT_TF32(af[0], *reinterpret_cast<const float*>(ap + kb0));
                    CVT_TF32(af[1], *reinterpret_cast<const float*>(ap + 1024 + kb0));
                    CVT_TF32(af[2], *reinterpret_cast<const float*>(ap + kb1));
                    CVT_TF32(af[3], *reinterpret_cast<const float*>(ap + 1024 + kb1));
                    #pragma unroll
                    for (int nt = 0; nt < 8; nt++)
                        MMA_TF32(acc[mt][nt], af, bf[nt]);
                }
            }
        }

        // HMMA issue implies all this stage's LDS completed -> safe to recycle.
        __syncwarp();
        if (lid == 0) MBARRIER_ARRIVE(sb + OFF_EMPTY + st * 8);
        if (++st == NSTAGE) { st = 0; ph ^= 1; }
    }

    // ---------------- epilogue: registers -> GMEM ----------------
    // c0,c1 -> (row = lane/4, cols 2*(lane%4)+{0,1}); c2,c3 -> row+8.
    const size_t rowBase = (size_t)b * kS + (size_t)tile * TILE_M
                         + (size_t)wid * 32 + (size_t)(lid >> 2);
    const int colBase = (lid & 3) * 2;
    #pragma unroll
    for (int mt = 0; mt < 2; mt++) {
        #pragma unroll
        for (int nt = 0; nt < 8; nt++) {
            const size_t r0 = rowBase + mt * 16;
            float* p0 = out + r0 * kOUT + nt * 8 + colBase;
            float* p1 = out + (r0 + 8) * kOUT + nt * 8 + colBase;
            *reinterpret_cast<float2*>(p0) = make_float2(acc[mt][nt][0], acc[mt][nt][1]);
            *reinterpret_cast<float2*>(p1) = make_float2(acc[mt][nt][2], acc[mt][nt][3]);
        }
    }
}

}  // namespace mlora

// ============================================================================
// Host side
// ============================================================================

typedef CUresult (*PFN_encodeTiled)(
    CUtensorMap*, CUtensorMapDataType, cuuint32_t, void*,
    const cuuint64_t*, const cuuint64_t*, const cuuint32_t*, const cuuint32_t*,
    CUtensorMapInterleave, CUtensorMapSwizzle, CUtensorMapL2promotion,
    CUtensorMapFloatOOBfill);

extern "C" void kernel_launch(void* const* d_in, const int* in_sizes, int n_in,
                              void* d_out, int out_size) {
    (void)in_sizes; (void)n_in; (void)out_size;
    const float* x   = (const float*)d_in[0];
    const int*   ids = (const int*)  d_in[1];
    const float* w   = (const float*)d_in[2];
    float*       out = (float*)d_out;

    PFN_encodeTiled enc = nullptr;
    {
        void* p = nullptr;
        cudaDriverEntryPointQueryResult qr;
#if CUDART_VERSION >= 12050
        cudaGetDriverEntryPointByVersion("cuTensorMapEncodeTiled", &p, 12000,
                                         cudaEnableDefault, &qr);
#else
        cudaGetDriverEntryPoint("cuTensorMapEncodeTiled", &p, cudaEnableDefault, &qr);
#endif
        enc = (PFN_encodeTiled)p;
    }

    CUtensorMap mapX, mapW;
    {
        // x: [B, S, IN] fp32 contiguous; dim0 = IN. Box = 32 x 128 (128B rows, SW128).
        cuuint64_t dims[3]    = {(cuuint64_t)mlora::kIN, (cuuint64_t)mlora::kS,
                                 (cuuint64_t)mlora::kB};
        cuuint64_t strides[2] = {(cuuint64_t)mlora::kIN * 4,
                                 (cuuint64_t)mlora::kS * mlora::kIN * 4};
        cuuint32_t box[3]     = {32, (cuuint32_t)mlora::TILE_M, 1};
        cuuint32_t es[3]      = {1, 1, 1};
        enc(&mapX, CU_TENSOR_MAP_DATA_TYPE_FLOAT32, 3, (void*)x,
            dims, strides, box, es,
            CU_TENSOR_MAP_INTERLEAVE_NONE, CU_TENSOR_MAP_SWIZZLE_128B,
            CU_TENSOR_MAP_L2_PROMOTION_L2_128B, CU_TENSOR_MAP_FLOAT_OOB_FILL_NONE);
    }
    {
        // weight: [L, OUT, IN] fp32 contiguous; dim0 = IN. Box = 32 x 64.
        cuuint64_t dims[3]    = {(cuuint64_t)mlora::kIN, (cuuint64_t)mlora::kOUT,
                                 (cuuint64_t)16};
        cuuint64_t strides[2] = {(cuuint64_t)mlora::kIN * 4,
                                 (cuuint64_t)mlora::kOUT * mlora::kIN * 4};
        cuuint32_t box[3]     = {32, (cuuint32_t)mlora::kOUT, 1};
        cuuint32_t es[3]      = {1, 1, 1};
        enc(&mapW, CU_TENSOR_MAP_DATA_TYPE_FLOAT32, 3, (void*)w,
            dims, strides, box, es,
            CU_TENSOR_MAP_INTERLEAVE_NONE, CU_TENSOR_MAP_SWIZZLE_128B,
            CU_TENSOR_MAP_L2_PROMOTION_L2_128B, CU_TENSOR_MAP_FLOAT_OOB_FILL_NONE);
    }

    cudaFuncSetAttribute(mlora::mlora_kernel,
                         cudaFuncAttributeMaxDynamicSharedMemorySize,
                         mlora::SMEM_TOTAL);

    const int grid = mlora::kB * (mlora::kS / mlora::TILE_M);  // 128
    mlora::mlora_kernel<<<grid, 160, mlora::SMEM_TOTAL>>>(mapX, mapW, ids, out);
}